// round 6
// baseline (speedup 1.0000x reference)
#include <cuda_runtime.h>
#include <cstdint>

#define C 64
#define MAXN 50000
#define MAXE 800000

// ---------------- device scratch (static: no allocation allowed) ----------------
__device__ float g_v[MAXN * C];
__device__ float g_Q1[MAXN * C];
__device__ float g_K1[MAXN * C];
__device__ float g_P1[MAXN * C];
__device__ float g_num[MAXN * C];
__device__ float g_den[MAXN * C];
__device__ float g_Mq_t[C * C];
__device__ float g_Mk_t[C * C];
__device__ float g_Win_t[C * C];
__device__ float g_Wlin_t[C * C];
__device__ float g_w2a_t[C * C];
__device__ float g_w2p_t[C * C];
__device__ float g_Wout_t[C * C];
__device__ float g_delta0[C];
__device__ float g_fWin[4096];
__device__ float g_fWlin[4096];
__device__ float g_fMq[4096];
__device__ float g_fMk[4096];
__device__ float g_fW2a[4096];
__device__ float g_fWout[4096];
// edge sorting scratch
__device__ int  g_cnt[MAXN];
__device__ int  g_pos[MAXN];
__device__ int2 g_es[MAXE];        // sorted (src, dst)

__device__ __forceinline__ unsigned f2tf32(float f) {
    unsigned r;
    asm("cvt.rna.tf32.f32 %0, %1;" : "=r"(r) : "f"(f));
    return r;
}

#define MMA_TF32(d, a, b0, b1)                                               \
    asm volatile("mma.sync.aligned.m16n8k8.row.col.f32.tf32.tf32.f32 "       \
                 "{%0,%1,%2,%3}, {%4,%5,%6,%7}, {%8,%9}, {%0,%1,%2,%3};"     \
                 : "+f"(d[0]), "+f"(d[1]), "+f"(d[2]), "+f"(d[3])            \
                 : "r"(a[0]), "r"(a[1]), "r"(a[2]), "r"(a[3]),               \
                   "r"(b0), "r"(b1))

// ---------------- sort kernels ---------------------------------------------------
__global__ void zero_cnt_kernel(int n) {
    int i = blockIdx.x * blockDim.x + threadIdx.x;
    if (i < n) g_cnt[i] = 0;
}
__global__ void hist_kernel(const int* __restrict__ dst, int E) {
    int e = blockIdx.x * blockDim.x + threadIdx.x;
    if (e < E) atomicAdd(&g_cnt[dst[e]], 1);
}
// single-block exclusive scan of g_cnt -> g_pos
__global__ void scan_kernel(int n) {
    __shared__ int wsum[32];
    __shared__ int carry;
    int tid = threadIdx.x, lane = tid & 31, wid = tid >> 5;
    if (tid == 0) carry = 0;
    __syncthreads();
    for (int bs = 0; bs < n; bs += 1024) {
        int i = bs + tid;
        int v = (i < n) ? g_cnt[i] : 0;
        int x = v;
        #pragma unroll
        for (int o = 1; o < 32; o <<= 1) {
            int t = __shfl_up_sync(0xffffffffu, x, o);
            if (lane >= o) x += t;
        }
        if (lane == 31) wsum[wid] = x;
        __syncthreads();
        if (wid == 0) {
            int y = wsum[lane];
            #pragma unroll
            for (int o = 1; o < 32; o <<= 1) {
                int t = __shfl_up_sync(0xffffffffu, y, o);
                if (lane >= o) y += t;
            }
            wsum[lane] = y;
        }
        __syncthreads();
        int incl = x + (wid > 0 ? wsum[wid - 1] : 0);
        if (i < n) g_pos[i] = carry + incl - v;
        int total = wsum[31];
        __syncthreads();
        if (tid == 0) carry += total;
        __syncthreads();
    }
}
__global__ void reorder_kernel(const int* __restrict__ src,
                               const int* __restrict__ dst, int E) {
    int e = blockIdx.x * blockDim.x + threadIdx.x;
    if (e < E) {
        int d = dst[e];
        int p = atomicAdd(&g_pos[d], 1);
        g_es[p] = make_int2(src[e], d);
    }
}

// ---------------- K0: weight prep ------------------------------------------------
__global__ void prep_kernel(const float* __restrict__ att_w1,
                            const float* __restrict__ W_dst,
                            const float* __restrict__ W_src,
                            const float* __restrict__ W_in,
                            const float* __restrict__ W_lin,
                            const float* __restrict__ att_w2,
                            const float* __restrict__ pos_w2,
                            const float* __restrict__ W_out,
                            const float* __restrict__ pos_b1,
                            const float* __restrict__ pos_b2)
{
    __shared__ float s_a[C * C];
    __shared__ float s_d[C * C];
    __shared__ float s_s[C * C];
    int tid = threadIdx.x;
    for (int t = tid; t < C * C; t += blockDim.x) {
        s_a[t] = att_w1[t];
        s_d[t] = W_dst[t];
        s_s[t] = W_src[t];
    }
    __syncthreads();
    for (int idx = tid; idx < C * C; idx += blockDim.x) {
        int t = idx >> 6, j = idx & 63;
        float aq = 0.f, ak = 0.f;
        #pragma unroll 8
        for (int u = 0; u < C; u++) {
            float a = s_a[t * C + u];
            aq = fmaf(a, s_d[u * C + j], aq);
            ak = fmaf(a, s_s[u * C + j], ak);
        }
        g_Mq_t[j * C + t] = aq;
        g_Mk_t[j * C + t] = ak;
    }
    for (int idx = tid; idx < C * C; idx += blockDim.x) {
        int cc = idx >> 6, j = idx & 63;
        g_Win_t[j * C + cc]  = W_in[idx];
        g_Wlin_t[j * C + cc] = W_lin[idx];
        g_w2a_t[j * C + cc]  = att_w2[idx];
        g_w2p_t[j * C + cc]  = pos_w2[idx];
        g_Wout_t[j * C + cc] = W_out[idx];
    }
    if (tid < C) {
        float acc = pos_b2[tid];
        #pragma unroll 8
        for (int j = 0; j < C; j++)
            acc = fmaf(fmaxf(pos_b1[j], 0.f), pos_w2[tid * C + j], acc);
        g_delta0[tid] = fmaxf(acc, 0.f);
    }
    __syncthreads();
    for (int t = tid; t < 2048; t += blockDim.x) {
        int kt   = t >> 8;
        int nt   = (t >> 5) & 7;
        int lane = t & 31;
        int kr = kt * 8 + (lane & 3);
        int nc = nt * 8 + (lane >> 2);
        int lo = kr * 64 + nc, hi = (kr + 4) * 64 + nc;
        ((float2*)g_fWin)[t]  = make_float2(__uint_as_float(f2tf32(g_Win_t[lo])),
                                            __uint_as_float(f2tf32(g_Win_t[hi])));
        ((float2*)g_fWlin)[t] = make_float2(__uint_as_float(f2tf32(g_Wlin_t[lo])),
                                            __uint_as_float(f2tf32(g_Wlin_t[hi])));
        ((float2*)g_fMq)[t]   = make_float2(__uint_as_float(f2tf32(g_Mq_t[lo])),
                                            __uint_as_float(f2tf32(g_Mq_t[hi])));
        ((float2*)g_fMk)[t]   = make_float2(__uint_as_float(f2tf32(g_Mk_t[lo])),
                                            __uint_as_float(f2tf32(g_Mk_t[hi])));
        ((float2*)g_fW2a)[t]  = make_float2(__uint_as_float(f2tf32(g_w2a_t[lo])),
                                            __uint_as_float(f2tf32(g_w2a_t[hi])));
        ((float2*)g_fWout)[t] = make_float2(__uint_as_float(f2tf32(g_Wout_t[lo])),
                                            __uint_as_float(f2tf32(g_Wout_t[hi])));
    }
}

// ---------------- K1: node kernel — 5 fused tf32 GEMMs over 64-node tiles -------
__global__ void __launch_bounds__(256)
node_kernel(const float* __restrict__ x,
            const float* __restrict__ pos,
            const float* __restrict__ pos_w1,
            const float* __restrict__ b_in,
            const float* __restrict__ att_b1,
            const float* __restrict__ att_b2,
            int n)
{
    extern __shared__ float sm[];
    float* xs = sm;
    float* hs = sm + 4352;
    float* vs = sm + 8704;
    int tid  = threadIdx.x;
    int lane = tid & 31;
    int wid  = tid >> 5;
    int base = blockIdx.x * 64;

    for (int t = tid; t < 1024; t += 256) {
        int row = t >> 4;
        int col = (t & 15) * 4;
        int node = base + row;
        float4 v4 = make_float4(0.f, 0.f, 0.f, 0.f);
        if (node < n) v4 = *(const float4*)(x + (size_t)node * C + col);
        float4 r;
        r.x = __uint_as_float(f2tf32(v4.x));
        r.y = __uint_as_float(f2tf32(v4.y));
        r.z = __uint_as_float(f2tf32(v4.z));
        r.w = __uint_as_float(f2tf32(v4.w));
        *(float4*)(xs + row * 68 + col) = r;
    }
    {
        int row = tid >> 2;
        int node = base + row;
        if (node < n) {
            float px = pos[(size_t)node * 3 + 0];
            float py = pos[(size_t)node * 3 + 1];
            float pz = pos[(size_t)node * 3 + 2];
            int c0 = (tid & 3) * 16;
            #pragma unroll
            for (int c = c0; c < c0 + 16; c++) {
                g_P1[(size_t)node * C + c] =
                    px * pos_w1[c * 3 + 0] + py * pos_w1[c * 3 + 1] + pz * pos_w1[c * 3 + 2];
            }
        }
    }
    __syncthreads();

    int r0 = (wid & 3) * 16;
    int nh = wid >> 2;
    int n0 = nh * 32;
    int rA = lane >> 2;
    int cb = 2 * (lane & 3);
    int rowg0 = base + r0 + rA;
    int rowg1 = rowg0 + 8;
    bool ok0 = rowg0 < n, ok1 = rowg1 < n;

    {
        float acc[4][4];
        #pragma unroll
        for (int nt = 0; nt < 4; nt++) {
            int col = n0 + nt * 8 + cb;
            float b0 = b_in[col], b1 = b_in[col + 1];
            acc[nt][0] = b0; acc[nt][1] = b1; acc[nt][2] = b0; acc[nt][3] = b1;
        }
        #pragma unroll
        for (int kt = 0; kt < 8; kt++) {
            int cA = kt * 8 + (lane & 3);
            unsigned a[4];
            a[0] = __float_as_uint(xs[(r0 + rA) * 68 + cA]);
            a[1] = __float_as_uint(xs[(r0 + 8 + rA) * 68 + cA]);
            a[2] = __float_as_uint(xs[(r0 + rA) * 68 + cA + 4]);
            a[3] = __float_as_uint(xs[(r0 + 8 + rA) * 68 + cA + 4]);
            #pragma unroll
            for (int nt = 0; nt < 4; nt++) {
                float2 b = ((const float2*)g_fWin)[(kt * 8 + nh * 4 + nt) * 32 + lane];
                MMA_TF32(acc[nt], a, __float_as_uint(b.x), __float_as_uint(b.y));
            }
        }
        #pragma unroll
        for (int nt = 0; nt < 4; nt++) {
            int col = n0 + nt * 8 + cb;
            hs[(r0 + rA) * 68 + col]       = __uint_as_float(f2tf32(fmaxf(acc[nt][0], 0.f)));
            hs[(r0 + rA) * 68 + col + 1]   = __uint_as_float(f2tf32(fmaxf(acc[nt][1], 0.f)));
            hs[(r0 + 8 + rA) * 68 + col]     = __uint_as_float(f2tf32(fmaxf(acc[nt][2], 0.f)));
            hs[(r0 + 8 + rA) * 68 + col + 1] = __uint_as_float(f2tf32(fmaxf(acc[nt][3], 0.f)));
        }
    }
    __syncthreads();

    {
        float acc[4][4];
        #pragma unroll
        for (int nt = 0; nt < 4; nt++)
            #pragma unroll
            for (int q = 0; q < 4; q++) acc[nt][q] = 0.f;
        #pragma unroll
        for (int kt = 0; kt < 8; kt++) {
            int cA = kt * 8 + (lane & 3);
            unsigned a[4];
            a[0] = __float_as_uint(hs[(r0 + rA) * 68 + cA]);
            a[1] = __float_as_uint(hs[(r0 + 8 + rA) * 68 + cA]);
            a[2] = __float_as_uint(hs[(r0 + rA) * 68 + cA + 4]);
            a[3] = __float_as_uint(hs[(r0 + 8 + rA) * 68 + cA + 4]);
            #pragma unroll
            for (int nt = 0; nt < 4; nt++) {
                float2 b = ((const float2*)g_fWlin)[(kt * 8 + nh * 4 + nt) * 32 + lane];
                MMA_TF32(acc[nt], a, __float_as_uint(b.x), __float_as_uint(b.y));
            }
        }
        #pragma unroll
        for (int nt = 0; nt < 4; nt++) {
            int col = n0 + nt * 8 + cb;
            vs[(r0 + rA) * 68 + col]         = acc[nt][0];
            vs[(r0 + rA) * 68 + col + 1]     = acc[nt][1];
            vs[(r0 + 8 + rA) * 68 + col]     = acc[nt][2];
            vs[(r0 + 8 + rA) * 68 + col + 1] = acc[nt][3];
            if (ok0) *(float2*)(g_v + (size_t)rowg0 * C + col) = make_float2(acc[nt][0], acc[nt][1]);
            if (ok1) *(float2*)(g_v + (size_t)rowg1 * C + col) = make_float2(acc[nt][2], acc[nt][3]);
        }
    }
    {
        float aq[4][4], ak[4][4];
        #pragma unroll
        for (int nt = 0; nt < 4; nt++)
            #pragma unroll
            for (int q = 0; q < 4; q++) { aq[nt][q] = 0.f; ak[nt][q] = 0.f; }
        #pragma unroll
        for (int kt = 0; kt < 8; kt++) {
            int cA = kt * 8 + (lane & 3);
            unsigned a[4];
            a[0] = __float_as_uint(hs[(r0 + rA) * 68 + cA]);
            a[1] = __float_as_uint(hs[(r0 + 8 + rA) * 68 + cA]);
            a[2] = __float_as_uint(hs[(r0 + rA) * 68 + cA + 4]);
            a[3] = __float_as_uint(hs[(r0 + 8 + rA) * 68 + cA + 4]);
            #pragma unroll
            for (int nt = 0; nt < 4; nt++) {
                float2 bq = ((const float2*)g_fMq)[(kt * 8 + nh * 4 + nt) * 32 + lane];
                float2 bk = ((const float2*)g_fMk)[(kt * 8 + nh * 4 + nt) * 32 + lane];
                MMA_TF32(aq[nt], a, __float_as_uint(bq.x), __float_as_uint(bq.y));
                MMA_TF32(ak[nt], a, __float_as_uint(bk.x), __float_as_uint(bk.y));
            }
        }
        #pragma unroll
        for (int nt = 0; nt < 4; nt++) {
            int col = n0 + nt * 8 + cb;
            float ba0 = att_b1[col], ba1 = att_b1[col + 1];
            xs[(r0 + rA) * 68 + col]       = __uint_as_float(f2tf32(fmaxf(aq[nt][0] - ak[nt][0] + ba0, 0.f)));
            xs[(r0 + rA) * 68 + col + 1]   = __uint_as_float(f2tf32(fmaxf(aq[nt][1] - ak[nt][1] + ba1, 0.f)));
            xs[(r0 + 8 + rA) * 68 + col]     = __uint_as_float(f2tf32(fmaxf(aq[nt][2] - ak[nt][2] + ba0, 0.f)));
            xs[(r0 + 8 + rA) * 68 + col + 1] = __uint_as_float(f2tf32(fmaxf(aq[nt][3] - ak[nt][3] + ba1, 0.f)));
            if (ok0) {
                *(float2*)(g_Q1 + (size_t)rowg0 * C + col) = make_float2(aq[nt][0], aq[nt][1]);
                *(float2*)(g_K1 + (size_t)rowg0 * C + col) = make_float2(ak[nt][0], ak[nt][1]);
            }
            if (ok1) {
                *(float2*)(g_Q1 + (size_t)rowg1 * C + col) = make_float2(aq[nt][2], aq[nt][3]);
                *(float2*)(g_K1 + (size_t)rowg1 * C + col) = make_float2(ak[nt][2], ak[nt][3]);
            }
        }
    }
    __syncthreads();

    {
        float acc[4][4];
        #pragma unroll
        for (int nt = 0; nt < 4; nt++) {
            int col = n0 + nt * 8 + cb;
            float b0 = att_b2[col], b1 = att_b2[col + 1];
            acc[nt][0] = b0; acc[nt][1] = b1; acc[nt][2] = b0; acc[nt][3] = b1;
        }
        #pragma unroll
        for (int kt = 0; kt < 8; kt++) {
            int cA = kt * 8 + (lane & 3);
            unsigned a[4];
            a[0] = __float_as_uint(xs[(r0 + rA) * 68 + cA]);
            a[1] = __float_as_uint(xs[(r0 + 8 + rA) * 68 + cA]);
            a[2] = __float_as_uint(xs[(r0 + rA) * 68 + cA + 4]);
            a[3] = __float_as_uint(xs[(r0 + 8 + rA) * 68 + cA + 4]);
            #pragma unroll
            for (int nt = 0; nt < 4; nt++) {
                float2 b = ((const float2*)g_fW2a)[(kt * 8 + nh * 4 + nt) * 32 + lane];
                MMA_TF32(acc[nt], a, __float_as_uint(b.x), __float_as_uint(b.y));
            }
        }
        #pragma unroll
        for (int nt = 0; nt < 4; nt++) {
            int col = n0 + nt * 8 + cb;
            float d0 = g_delta0[col], d1 = g_delta0[col + 1];
            float e0 = __expf(fmaxf(acc[nt][0], 0.f));
            float e1 = __expf(fmaxf(acc[nt][1], 0.f));
            float e2 = __expf(fmaxf(acc[nt][2], 0.f));
            float e3 = __expf(fmaxf(acc[nt][3], 0.f));
            if (ok0) {
                float v0 = vs[(r0 + rA) * 68 + col];
                float v1 = vs[(r0 + rA) * 68 + col + 1];
                *(float2*)(g_den + (size_t)rowg0 * C + col) = make_float2(e0, e1);
                *(float2*)(g_num + (size_t)rowg0 * C + col) = make_float2(e0 * (v0 + d0), e1 * (v1 + d1));
            }
            if (ok1) {
                float v2 = vs[(r0 + 8 + rA) * 68 + col];
                float v3 = vs[(r0 + 8 + rA) * 68 + col + 1];
                *(float2*)(g_den + (size_t)rowg1 * C + col) = make_float2(e2, e3);
                *(float2*)(g_num + (size_t)rowg1 * C + col) = make_float2(e2 * (v2 + d0), e3 * (v3 + d1));
            }
        }
    }
}

// ---------------- K2: edge kernel — dst-sorted, pipelined, merged scatter -------
__global__ void __launch_bounds__(256, 2)
edge_kernel(const float* __restrict__ att_b1, const float* __restrict__ pos_b1,
            const float* __restrict__ att_b2, const float* __restrict__ pos_b2,
            int E)
{
    extern __shared__ float smE[];
    float* hidA = smE;
    float* hidP = smE + 4352;
    float* exA  = smE + 8704;
    float* dlP  = smE + 13056;
    int2*  edB  = (int2*)(smE + 17408);   // [2][64]

    int tid  = threadIdx.x;
    int lane = tid & 31;
    int wid  = tid >> 5;
    bool isA = (wid < 4);
    int sub  = wid & 3;
    int n0b  = (sub & 1) * 32;
    int mp   = sub >> 1;
    int r0m  = mp * 16;
    int r1m  = (mp + 2) * 16;

    const float* w2 = isA ? g_w2a_t : g_w2p_t;
    const float* b2 = isA ? att_b2 : pos_b2;
    float* hid = isA ? hidA : hidP;
    float* res = isA ? exA  : dlP;

    unsigned bB[8][4][2];
    #pragma unroll
    for (int kt = 0; kt < 8; kt++) {
        #pragma unroll
        for (int nt = 0; nt < 4; nt++) {
            int k0 = kt * 8, n0 = n0b + nt * 8;
            bB[kt][nt][0] = f2tf32(w2[(k0 + (lane & 3)) * 64 + n0 + (lane >> 2)]);
            bB[kt][nt][1] = f2tf32(w2[(k0 + (lane & 3) + 4) * 64 + n0 + (lane >> 2)]);
        }
    }
    float bias0[4], bias1[4];
    #pragma unroll
    for (int nt = 0; nt < 4; nt++) {
        int col = n0b + nt * 8 + 2 * (lane & 3);
        bias0[nt] = b2[col];
        bias1[nt] = b2[col + 1];
    }

    // gather/scatter role: group of 16 lanes owns 4 CONSECUTIVE edges
    int grp = tid >> 4;          // 0..15
    int js  = (tid & 15) << 2;   // col slice
    int eb  = grp << 2;          // local edge base (consecutive)
    float4 ba1 = *(const float4*)(att_b1 + js);
    float4 bp1 = *(const float4*)(pos_b1 + js);

    int sPrev[4], dPrev[4];
    #pragma unroll
    for (int k = 0; k < 4; k++) dPrev[k] = -1;

    int ntiles = (E + 63) >> 6;

    {
        int base = blockIdx.x << 6;
        if (tid < 64) {
            int e = base + tid;
            edB[tid] = (e < E) ? g_es[e] : make_int2(0, -1);
        }
    }
    __syncthreads();

    int it = 0;
    for (int tile = blockIdx.x; tile < ntiles; tile += gridDim.x, it ^= 1) {
        // ===== PHASE A: merged scatter(prev) + gather(cur) + idx prefetch =====
        {
            float4 nAcc, dAcc;
            int curD = -1;
            #pragma unroll
            for (int k = 0; k < 4; k++) {
                int d = dPrev[k];
                if (d >= 0) {
                    int e = eb + k;
                    float4 ex = *(const float4*)(exA + e * 68 + js);
                    float4 dl = *(const float4*)(dlP + e * 68 + js);
                    float4 vv = *(const float4*)(g_v + (size_t)sPrev[k] * C + js);
                    float4 nv;
                    nv.x = ex.x * (vv.x + dl.x);
                    nv.y = ex.y * (vv.y + dl.y);
                    nv.z = ex.z * (vv.z + dl.z);
                    nv.w = ex.w * (vv.w + dl.w);
                    if (d == curD) {
                        nAcc.x += nv.x; nAcc.y += nv.y; nAcc.z += nv.z; nAcc.w += nv.w;
                        dAcc.x += ex.x; dAcc.y += ex.y; dAcc.z += ex.z; dAcc.w += ex.w;
                    } else {
                        if (curD >= 0) {
                            float* nr = g_num + (size_t)curD * C + js;
                            float* dr = g_den + (size_t)curD * C + js;
                            asm volatile("red.global.add.v4.f32 [%0], {%1,%2,%3,%4};"
                                         :: "l"(nr), "f"(nAcc.x), "f"(nAcc.y), "f"(nAcc.z), "f"(nAcc.w)
                                         : "memory");
                            asm volatile("red.global.add.v4.f32 [%0], {%1,%2,%3,%4};"
                                         :: "l"(dr), "f"(dAcc.x), "f"(dAcc.y), "f"(dAcc.z), "f"(dAcc.w)
                                         : "memory");
                        }
                        curD = d;
                        nAcc = nv;
                        dAcc = ex;
                    }
                }
            }
            if (curD >= 0) {
                float* nr = g_num + (size_t)curD * C + js;
                float* dr = g_den + (size_t)curD * C + js;
                asm volatile("red.global.add.v4.f32 [%0], {%1,%2,%3,%4};"
                             :: "l"(nr), "f"(nAcc.x), "f"(nAcc.y), "f"(nAcc.z), "f"(nAcc.w)
                             : "memory");
                asm volatile("red.global.add.v4.f32 [%0], {%1,%2,%3,%4};"
                             :: "l"(dr), "f"(dAcc.x), "f"(dAcc.y), "f"(dAcc.z), "f"(dAcc.w)
                             : "memory");
            }
        }
        // gather of current tile: dst-side loads dedup'd across consecutive edges
        {
            int dLast = -1;
            float4 qv, pd;
            #pragma unroll
            for (int k = 0; k < 4; k++) {
                int e = eb + k;
                int2 ed = edB[it * 64 + e];
                int s = ed.x, d = ed.y;
                sPrev[k] = s;
                dPrev[k] = d;
                int dc = d < 0 ? 0 : d;
                if (dc != dLast) {
                    qv = *(const float4*)(g_Q1 + (size_t)dc * C + js);
                    pd = *(const float4*)(g_P1 + (size_t)dc * C + js);
                    dLast = dc;
                }
                float4 kv = *(const float4*)(g_K1 + (size_t)s * C + js);
                float4 ps = *(const float4*)(g_P1 + (size_t)s * C + js);
                float4 ra, rp;
                ra.x = __uint_as_float(f2tf32(fmaxf(qv.x - kv.x + ba1.x, 0.f)));
                ra.y = __uint_as_float(f2tf32(fmaxf(qv.y - kv.y + ba1.y, 0.f)));
                ra.z = __uint_as_float(f2tf32(fmaxf(qv.z - kv.z + ba1.z, 0.f)));
                ra.w = __uint_as_float(f2tf32(fmaxf(qv.w - kv.w + ba1.w, 0.f)));
                rp.x = __uint_as_float(f2tf32(fmaxf(pd.x - ps.x + bp1.x, 0.f)));
                rp.y = __uint_as_float(f2tf32(fmaxf(pd.y - ps.y + bp1.y, 0.f)));
                rp.z = __uint_as_float(f2tf32(fmaxf(pd.z - ps.z + bp1.z, 0.f)));
                rp.w = __uint_as_float(f2tf32(fmaxf(pd.w - ps.w + bp1.w, 0.f)));
                if (d < 0) {
                    ra = make_float4(0.f, 0.f, 0.f, 0.f);
                    rp = ra;
                }
                *(float4*)(hidA + e * 68 + js) = ra;
                *(float4*)(hidP + e * 68 + js) = rp;
            }
        }
        {
            int ntile = tile + gridDim.x;
            if (ntile < ntiles && tid < 64) {
                int e = (ntile << 6) + tid;
                edB[(it ^ 1) * 64 + tid] = (e < E) ? g_es[e] : make_int2(0, -1);
            }
        }
        __syncthreads();

        // ===== PHASE B: tensor-core MMA + epilogue -> exA/dlP =====
        float acc[2][4][4];
        #pragma unroll
        for (int s2 = 0; s2 < 2; s2++)
            #pragma unroll
            for (int nt = 0; nt < 4; nt++) {
                acc[s2][nt][0] = bias0[nt];
                acc[s2][nt][1] = bias1[nt];
                acc[s2][nt][2] = bias0[nt];
                acc[s2][nt][3] = bias1[nt];
            }
        int rA = lane >> 2;
        #pragma unroll
        for (int kt = 0; kt < 8; kt++) {
            int cA = kt * 8 + (lane & 3);
            unsigned a[2][4];
            a[0][0] = __float_as_uint(hid[(r0m + rA) * 68 + cA]);
            a[0][1] = __float_as_uint(hid[(r0m + 8 + rA) * 68 + cA]);
            a[0][2] = __float_as_uint(hid[(r0m + rA) * 68 + cA + 4]);
            a[0][3] = __float_as_uint(hid[(r0m + 8 + rA) * 68 + cA + 4]);
            a[1][0] = __float_as_uint(hid[(r1m + rA) * 68 + cA]);
            a[1][1] = __float_as_uint(hid[(r1m + 8 + rA) * 68 + cA]);
            a[1][2] = __float_as_uint(hid[(r1m + rA) * 68 + cA + 4]);
            a[1][3] = __float_as_uint(hid[(r1m + 8 + rA) * 68 + cA + 4]);
            #pragma unroll
            for (int s2 = 0; s2 < 2; s2++)
                #pragma unroll
                for (int nt = 0; nt < 4; nt++)
                    MMA_TF32(acc[s2][nt], a[s2], bB[kt][nt][0], bB[kt][nt][1]);
        }
        {
            int cbv = 2 * (lane & 3);
            #pragma unroll
            for (int s2 = 0; s2 < 2; s2++) {
                int rb = (s2 ? r1m : r0m) + rA;
                #pragma unroll
                for (int nt = 0; nt < 4; nt++) {
                    int col = n0b + nt * 8 + cbv;
                    float v0, v1, v2, v3;
                    if (isA) {
                        v0 = __expf(fmaxf(acc[s2][nt][0], 0.f));
                        v1 = __expf(fmaxf(acc[s2][nt][1], 0.f));
                        v2 = __expf(fmaxf(acc[s2][nt][2], 0.f));
                        v3 = __expf(fmaxf(acc[s2][nt][3], 0.f));
                    } else {
                        v0 = fmaxf(acc[s2][nt][0], 0.f);
                        v1 = fmaxf(acc[s2][nt][1], 0.f);
                        v2 = fmaxf(acc[s2][nt][2], 0.f);
                        v3 = fmaxf(acc[s2][nt][3], 0.f);
                    }
                    res[rb * 68 + col]           = v0;
                    res[rb * 68 + col + 1]       = v1;
                    res[(rb + 8) * 68 + col]     = v2;
                    res[(rb + 8) * 68 + col + 1] = v3;
                }
            }
        }
        __syncthreads();
    }

    // ===== pipeline drain: merged scatter of the final tile =====
    {
        float4 nAcc, dAcc;
        int curD = -1;
        #pragma unroll
        for (int k = 0; k < 4; k++) {
            int d = dPrev[k];
            if (d >= 0) {
                int e = eb + k;
                float4 ex = *(const float4*)(exA + e * 68 + js);
                float4 dl = *(const float4*)(dlP + e * 68 + js);
                float4 vv = *(const float4*)(g_v + (size_t)sPrev[k] * C + js);
                float4 nv;
                nv.x = ex.x * (vv.x + dl.x);
                nv.y = ex.y * (vv.y + dl.y);
                nv.z = ex.z * (vv.z + dl.z);
                nv.w = ex.w * (vv.w + dl.w);
                if (d == curD) {
                    nAcc.x += nv.x; nAcc.y += nv.y; nAcc.z += nv.z; nAcc.w += nv.w;
                    dAcc.x += ex.x; dAcc.y += ex.y; dAcc.z += ex.z; dAcc.w += ex.w;
                } else {
                    if (curD >= 0) {
                        float* nr = g_num + (size_t)curD * C + js;
                        float* dr = g_den + (size_t)curD * C + js;
                        asm volatile("red.global.add.v4.f32 [%0], {%1,%2,%3,%4};"
                                     :: "l"(nr), "f"(nAcc.x), "f"(nAcc.y), "f"(nAcc.z), "f"(nAcc.w)
                                     : "memory");
                        asm volatile("red.global.add.v4.f32 [%0], {%1,%2,%3,%4};"
                                     :: "l"(dr), "f"(dAcc.x), "f"(dAcc.y), "f"(dAcc.z), "f"(dAcc.w)
                                     : "memory");
                    }
                    curD = d;
                    nAcc = nv;
                    dAcc = ex;
                }
            }
        }
        if (curD >= 0) {
            float* nr = g_num + (size_t)curD * C + js;
            float* dr = g_den + (size_t)curD * C + js;
            asm volatile("red.global.add.v4.f32 [%0], {%1,%2,%3,%4};"
                         :: "l"(nr), "f"(nAcc.x), "f"(nAcc.y), "f"(nAcc.z), "f"(nAcc.w)
                         : "memory");
            asm volatile("red.global.add.v4.f32 [%0], {%1,%2,%3,%4};"
                         :: "l"(dr), "f"(dAcc.x), "f"(dAcc.y), "f"(dAcc.z), "f"(dAcc.w)
                         : "memory");
        }
    }
}

// ---------------- K3: out kernel — tf32 MMA over 64-node tiles ------------------
__global__ void __launch_bounds__(256)
out_kernel(const float* __restrict__ b_out, float* __restrict__ out, int n)
{
    __shared__ float rs[64 * 68];
    int tid  = threadIdx.x;
    int lane = tid & 31;
    int wid  = tid >> 5;
    int base = blockIdx.x * 64;

    for (int t = tid; t < 1024; t += 256) {
        int row = t >> 4;
        int col = (t & 15) * 4;
        int node = base + row;
        float4 r = make_float4(0.f, 0.f, 0.f, 0.f);
        if (node < n) {
            float4 nu = *(const float4*)(g_num + (size_t)node * C + col);
            float4 de = *(const float4*)(g_den + (size_t)node * C + col);
            r.x = __uint_as_float(f2tf32(nu.x / (de.x + 1e-16f)));
            r.y = __uint_as_float(f2tf32(nu.y / (de.y + 1e-16f)));
            r.z = __uint_as_float(f2tf32(nu.z / (de.z + 1e-16f)));
            r.w = __uint_as_float(f2tf32(nu.w / (de.w + 1e-16f)));
        }
        *(float4*)(rs + row * 68 + col) = r;
    }
    __syncthreads();

    int r0 = (wid & 3) * 16;
    int nh = wid >> 2;
    int n0 = nh * 32;
    int rA = lane >> 2;
    int cb = 2 * (lane & 3);
    int rowg0 = base + r0 + rA;
    int rowg1 = rowg0 + 8;

    float acc[4][4];
    #pragma unroll
    for (int nt = 0; nt < 4; nt++) {
        int col = n0 + nt * 8 + cb;
        float b0 = b_out[col], b1 = b_out[col + 1];
        acc[nt][0] = b0; acc[nt][1] = b1; acc[nt][2] = b0; acc[nt][3] = b1;
    }
    #pragma unroll
    for (int kt = 0; kt < 8; kt++) {
        int cA = kt * 8 + (lane & 3);
        unsigned a[4];
        a[0] = __float_as_uint(rs[(r0 + rA) * 68 + cA]);
        a[1] = __float_as_uint(rs[(r0 + 8 + rA) * 68 + cA]);
        a[2] = __float_as_uint(rs[(r0 + rA) * 68 + cA + 4]);
        a[3] = __float_as_uint(rs[(r0 + 8 + rA) * 68 + cA + 4]);
        #pragma unroll
        for (int nt = 0; nt < 4; nt++) {
            float2 b = ((const float2*)g_fWout)[(kt * 8 + nh * 4 + nt) * 32 + lane];
            MMA_TF32(acc[nt], a, __float_as_uint(b.x), __float_as_uint(b.y));
        }
    }
    #pragma unroll
    for (int nt = 0; nt < 4; nt++) {
        int col = n0 + nt * 8 + cb;
        if (rowg0 < n)
            *(float2*)(out + (size_t)rowg0 * C + col) =
                make_float2(fmaxf(acc[nt][0], 0.f), fmaxf(acc[nt][1], 0.f));
        if (rowg1 < n)
            *(float2*)(out + (size_t)rowg1 * C + col) =
                make_float2(fmaxf(acc[nt][2], 0.f), fmaxf(acc[nt][3], 0.f));
    }
}

// ---------------- launch --------------------------------------------------------
extern "C" void kernel_launch(void* const* d_in, const int* in_sizes, int n_in,
                              void* d_out, int out_size)
{
    const float* x      = (const float*)d_in[0];
    const float* pos    = (const float*)d_in[1];
    const int*   ei     = (const int*)  d_in[2];
    const float* W_in   = (const float*)d_in[3];
    const float* b_in   = (const float*)d_in[4];
    const float* W_out  = (const float*)d_in[5];
    const float* b_out  = (const float*)d_in[6];
    const float* W_lin  = (const float*)d_in[7];
    const float* W_src  = (const float*)d_in[8];
    const float* W_dst  = (const float*)d_in[9];
    const float* pos_w1 = (const float*)d_in[10];
    const float* pos_b1 = (const float*)d_in[11];
    const float* pos_w2 = (const float*)d_in[12];
    const float* pos_b2 = (const float*)d_in[13];
    const float* att_w1 = (const float*)d_in[14];
    const float* att_b1 = (const float*)d_in[15];
    const float* att_w2 = (const float*)d_in[16];
    const float* att_b2 = (const float*)d_in[17];

    int n = in_sizes[0] / C;
    int E = in_sizes[2] / 2;
    const int* srcArr = ei;
    const int* dstArr = ei + E;

    size_t smemNode = (size_t)(3 * 64 * 68) * sizeof(float);          // 52224
    size_t smemEdge = (size_t)(4 * 64 * 68) * sizeof(float) + 1024;   // 70656
    cudaFuncSetAttribute(node_kernel, cudaFuncAttributeMaxDynamicSharedMemorySize, (int)smemNode);
    cudaFuncSetAttribute(edge_kernel, cudaFuncAttributeMaxDynamicSharedMemorySize, (int)smemEdge);

    int tilesN = (n + 63) / 64;

    // edge sort by dst (counting sort)
    zero_cnt_kernel<<<(n + 255) / 256, 256>>>(n);
    hist_kernel<<<(E + 255) / 256, 256>>>(dstArr, E);
    scan_kernel<<<1, 1024>>>(n);
    reorder_kernel<<<(E + 255) / 256, 256>>>(srcArr, dstArr, E);

    prep_kernel<<<1, 256>>>(att_w1, W_dst, W_src, W_in, W_lin, att_w2, pos_w2, W_out,
                            pos_b1, pos_b2);
    node_kernel<<<tilesN, 256, smemNode>>>(x, pos, pos_w1, b_in, att_b1, att_b2, n);
    edge_kernel<<<296, 256, smemEdge>>>(att_b1, pos_b1, att_b2, pos_b2, E);
    out_kernel<<<tilesN, 256>>>(b_out, (float*)d_out, n);
}

// round 7
// speedup vs baseline: 1.0091x; 1.0091x over previous
#include <cuda_runtime.h>
#include <cstdint>

#define C 64
#define MAXN 50000
#define MAXE 800000

// ---------------- device scratch (static: no allocation allowed) ----------------
__device__ float g_v[MAXN * C];
__device__ float g_Q1[MAXN * C];
__device__ float g_K1[MAXN * C];
__device__ float g_P1[MAXN * C];
__device__ float g_num[MAXN * C];
__device__ float g_den[MAXN * C];
__device__ float g_Mq_t[C * C];
__device__ float g_Mk_t[C * C];
__device__ float g_Win_t[C * C];
__device__ float g_Wlin_t[C * C];
__device__ float g_w2a_t[C * C];
__device__ float g_w2p_t[C * C];
__device__ float g_Wout_t[C * C];
__device__ float g_delta0[C];
__device__ float g_fWin[4096];
__device__ float g_fWlin[4096];
__device__ float g_fMq[4096];
__device__ float g_fMk[4096];
__device__ float g_fW2a[4096];
__device__ float g_fWout[4096];
// edge sorting scratch
__device__ int  g_cnt[MAXN];
__device__ int  g_pos[MAXN];
__device__ int2 g_es[MAXE];        // sorted (src, dst)

__device__ __forceinline__ unsigned f2tf32(float f) {
    unsigned r;
    asm("cvt.rna.tf32.f32 %0, %1;" : "=r"(r) : "f"(f));
    return r;
}

#define MMA_TF32(d, a, b0, b1)                                               \
    asm volatile("mma.sync.aligned.m16n8k8.row.col.f32.tf32.tf32.f32 "       \
                 "{%0,%1,%2,%3}, {%4,%5,%6,%7}, {%8,%9}, {%0,%1,%2,%3};"     \
                 : "+f"(d[0]), "+f"(d[1]), "+f"(d[2]), "+f"(d[3])            \
                 : "r"(a[0]), "r"(a[1]), "r"(a[2]), "r"(a[3]),               \
                   "r"(b0), "r"(b1))

// ---------------- sort kernels ---------------------------------------------------
__global__ void zero_cnt_kernel(int n) {
    int i = blockIdx.x * blockDim.x + threadIdx.x;
    if (i < n) g_cnt[i] = 0;
}
__global__ void hist_kernel(const int* __restrict__ dst, int E) {
    int e = blockIdx.x * blockDim.x + threadIdx.x;
    if (e < E) atomicAdd(&g_cnt[dst[e]], 1);
}
// single-block exclusive scan of g_cnt -> g_pos
__global__ void scan_kernel(int n) {
    __shared__ int wsum[32];
    __shared__ int carry;
    int tid = threadIdx.x, lane = tid & 31, wid = tid >> 5;
    if (tid == 0) carry = 0;
    __syncthreads();
    for (int bs = 0; bs < n; bs += 1024) {
        int i = bs + tid;
        int v = (i < n) ? g_cnt[i] : 0;
        int x = v;
        #pragma unroll
        for (int o = 1; o < 32; o <<= 1) {
            int t = __shfl_up_sync(0xffffffffu, x, o);
            if (lane >= o) x += t;
        }
        if (lane == 31) wsum[wid] = x;
        __syncthreads();
        if (wid == 0) {
            int y = wsum[lane];
            #pragma unroll
            for (int o = 1; o < 32; o <<= 1) {
                int t = __shfl_up_sync(0xffffffffu, y, o);
                if (lane >= o) y += t;
            }
            wsum[lane] = y;
        }
        __syncthreads();
        int incl = x + (wid > 0 ? wsum[wid - 1] : 0);
        if (i < n) g_pos[i] = carry + incl - v;
        int total = wsum[31];
        __syncthreads();
        if (tid == 0) carry += total;
        __syncthreads();
    }
}
__global__ void reorder_kernel(const int* __restrict__ src,
                               const int* __restrict__ dst, int E) {
    int e = blockIdx.x * blockDim.x + threadIdx.x;
    if (e < E) {
        int d = dst[e];
        int p = atomicAdd(&g_pos[d], 1);
        g_es[p] = make_int2(src[e], d);
    }
}

// ---------------- K0: weight prep ------------------------------------------------
__global__ void prep_kernel(const float* __restrict__ att_w1,
                            const float* __restrict__ W_dst,
                            const float* __restrict__ W_src,
                            const float* __restrict__ W_in,
                            const float* __restrict__ W_lin,
                            const float* __restrict__ att_w2,
                            const float* __restrict__ pos_w2,
                            const float* __restrict__ W_out,
                            const float* __restrict__ pos_b1,
                            const float* __restrict__ pos_b2)
{
    __shared__ float s_a[C * C];
    __shared__ float s_d[C * C];
    __shared__ float s_s[C * C];
    int tid = threadIdx.x;
    for (int t = tid; t < C * C; t += blockDim.x) {
        s_a[t] = att_w1[t];
        s_d[t] = W_dst[t];
        s_s[t] = W_src[t];
    }
    __syncthreads();
    for (int idx = tid; idx < C * C; idx += blockDim.x) {
        int t = idx >> 6, j = idx & 63;
        float aq = 0.f, ak = 0.f;
        #pragma unroll 8
        for (int u = 0; u < C; u++) {
            float a = s_a[t * C + u];
            aq = fmaf(a, s_d[u * C + j], aq);
            ak = fmaf(a, s_s[u * C + j], ak);
        }
        g_Mq_t[j * C + t] = aq;
        g_Mk_t[j * C + t] = ak;
    }
    for (int idx = tid; idx < C * C; idx += blockDim.x) {
        int cc = idx >> 6, j = idx & 63;
        g_Win_t[j * C + cc]  = W_in[idx];
        g_Wlin_t[j * C + cc] = W_lin[idx];
        g_w2a_t[j * C + cc]  = att_w2[idx];
        g_w2p_t[j * C + cc]  = pos_w2[idx];
        g_Wout_t[j * C + cc] = W_out[idx];
    }
    if (tid < C) {
        float acc = pos_b2[tid];
        #pragma unroll 8
        for (int j = 0; j < C; j++)
            acc = fmaf(fmaxf(pos_b1[j], 0.f), pos_w2[tid * C + j], acc);
        g_delta0[tid] = fmaxf(acc, 0.f);
    }
    __syncthreads();
    for (int t = tid; t < 2048; t += blockDim.x) {
        int kt   = t >> 8;
        int nt   = (t >> 5) & 7;
        int lane = t & 31;
        int kr = kt * 8 + (lane & 3);
        int nc = nt * 8 + (lane >> 2);
        int lo = kr * 64 + nc, hi = (kr + 4) * 64 + nc;
        ((float2*)g_fWin)[t]  = make_float2(__uint_as_float(f2tf32(g_Win_t[lo])),
                                            __uint_as_float(f2tf32(g_Win_t[hi])));
        ((float2*)g_fWlin)[t] = make_float2(__uint_as_float(f2tf32(g_Wlin_t[lo])),
                                            __uint_as_float(f2tf32(g_Wlin_t[hi])));
        ((float2*)g_fMq)[t]   = make_float2(__uint_as_float(f2tf32(g_Mq_t[lo])),
                                            __uint_as_float(f2tf32(g_Mq_t[hi])));
        ((float2*)g_fMk)[t]   = make_float2(__uint_as_float(f2tf32(g_Mk_t[lo])),
                                            __uint_as_float(f2tf32(g_Mk_t[hi])));
        ((float2*)g_fW2a)[t]  = make_float2(__uint_as_float(f2tf32(g_w2a_t[lo])),
                                            __uint_as_float(f2tf32(g_w2a_t[hi])));
        ((float2*)g_fWout)[t] = make_float2(__uint_as_float(f2tf32(g_Wout_t[lo])),
                                            __uint_as_float(f2tf32(g_Wout_t[hi])));
    }
}

// ---------------- K1: node kernel — 5 fused tf32 GEMMs over 64-node tiles -------
__global__ void __launch_bounds__(256)
node_kernel(const float* __restrict__ x,
            const float* __restrict__ pos,
            const float* __restrict__ pos_w1,
            const float* __restrict__ b_in,
            const float* __restrict__ att_b1,
            const float* __restrict__ att_b2,
            int n)
{
    extern __shared__ float sm[];
    float* xs = sm;
    float* hs = sm + 4352;
    float* vs = sm + 8704;
    int tid  = threadIdx.x;
    int lane = tid & 31;
    int wid  = tid >> 5;
    int base = blockIdx.x * 64;

    for (int t = tid; t < 1024; t += 256) {
        int row = t >> 4;
        int col = (t & 15) * 4;
        int node = base + row;
        float4 v4 = make_float4(0.f, 0.f, 0.f, 0.f);
        if (node < n) v4 = *(const float4*)(x + (size_t)node * C + col);
        float4 r;
        r.x = __uint_as_float(f2tf32(v4.x));
        r.y = __uint_as_float(f2tf32(v4.y));
        r.z = __uint_as_float(f2tf32(v4.z));
        r.w = __uint_as_float(f2tf32(v4.w));
        *(float4*)(xs + row * 68 + col) = r;
    }
    {
        int row = tid >> 2;
        int node = base + row;
        if (node < n) {
            float px = pos[(size_t)node * 3 + 0];
            float py = pos[(size_t)node * 3 + 1];
            float pz = pos[(size_t)node * 3 + 2];
            int c0 = (tid & 3) * 16;
            #pragma unroll
            for (int c = c0; c < c0 + 16; c++) {
                g_P1[(size_t)node * C + c] =
                    px * pos_w1[c * 3 + 0] + py * pos_w1[c * 3 + 1] + pz * pos_w1[c * 3 + 2];
            }
        }
    }
    __syncthreads();

    int r0 = (wid & 3) * 16;
    int nh = wid >> 2;
    int n0 = nh * 32;
    int rA = lane >> 2;
    int cb = 2 * (lane & 3);
    int rowg0 = base + r0 + rA;
    int rowg1 = rowg0 + 8;
    bool ok0 = rowg0 < n, ok1 = rowg1 < n;

    {
        float acc[4][4];
        #pragma unroll
        for (int nt = 0; nt < 4; nt++) {
            int col = n0 + nt * 8 + cb;
            float b0 = b_in[col], b1 = b_in[col + 1];
            acc[nt][0] = b0; acc[nt][1] = b1; acc[nt][2] = b0; acc[nt][3] = b1;
        }
        #pragma unroll
        for (int kt = 0; kt < 8; kt++) {
            int cA = kt * 8 + (lane & 3);
            unsigned a[4];
            a[0] = __float_as_uint(xs[(r0 + rA) * 68 + cA]);
            a[1] = __float_as_uint(xs[(r0 + 8 + rA) * 68 + cA]);
            a[2] = __float_as_uint(xs[(r0 + rA) * 68 + cA + 4]);
            a[3] = __float_as_uint(xs[(r0 + 8 + rA) * 68 + cA + 4]);
            #pragma unroll
            for (int nt = 0; nt < 4; nt++) {
                float2 b = ((const float2*)g_fWin)[(kt * 8 + nh * 4 + nt) * 32 + lane];
                MMA_TF32(acc[nt], a, __float_as_uint(b.x), __float_as_uint(b.y));
            }
        }
        #pragma unroll
        for (int nt = 0; nt < 4; nt++) {
            int col = n0 + nt * 8 + cb;
            hs[(r0 + rA) * 68 + col]       = __uint_as_float(f2tf32(fmaxf(acc[nt][0], 0.f)));
            hs[(r0 + rA) * 68 + col + 1]   = __uint_as_float(f2tf32(fmaxf(acc[nt][1], 0.f)));
            hs[(r0 + 8 + rA) * 68 + col]     = __uint_as_float(f2tf32(fmaxf(acc[nt][2], 0.f)));
            hs[(r0 + 8 + rA) * 68 + col + 1] = __uint_as_float(f2tf32(fmaxf(acc[nt][3], 0.f)));
        }
    }
    __syncthreads();

    {
        float acc[4][4];
        #pragma unroll
        for (int nt = 0; nt < 4; nt++)
            #pragma unroll
            for (int q = 0; q < 4; q++) acc[nt][q] = 0.f;
        #pragma unroll
        for (int kt = 0; kt < 8; kt++) {
            int cA = kt * 8 + (lane & 3);
            unsigned a[4];
            a[0] = __float_as_uint(hs[(r0 + rA) * 68 + cA]);
            a[1] = __float_as_uint(hs[(r0 + 8 + rA) * 68 + cA]);
            a[2] = __float_as_uint(hs[(r0 + rA) * 68 + cA + 4]);
            a[3] = __float_as_uint(hs[(r0 + 8 + rA) * 68 + cA + 4]);
            #pragma unroll
            for (int nt = 0; nt < 4; nt++) {
                float2 b = ((const float2*)g_fWlin)[(kt * 8 + nh * 4 + nt) * 32 + lane];
                MMA_TF32(acc[nt], a, __float_as_uint(b.x), __float_as_uint(b.y));
            }
        }
        #pragma unroll
        for (int nt = 0; nt < 4; nt++) {
            int col = n0 + nt * 8 + cb;
            vs[(r0 + rA) * 68 + col]         = acc[nt][0];
            vs[(r0 + rA) * 68 + col + 1]     = acc[nt][1];
            vs[(r0 + 8 + rA) * 68 + col]     = acc[nt][2];
            vs[(r0 + 8 + rA) * 68 + col + 1] = acc[nt][3];
            if (ok0) *(float2*)(g_v + (size_t)rowg0 * C + col) = make_float2(acc[nt][0], acc[nt][1]);
            if (ok1) *(float2*)(g_v + (size_t)rowg1 * C + col) = make_float2(acc[nt][2], acc[nt][3]);
        }
    }
    {
        float aq[4][4], ak[4][4];
        #pragma unroll
        for (int nt = 0; nt < 4; nt++)
            #pragma unroll
            for (int q = 0; q < 4; q++) { aq[nt][q] = 0.f; ak[nt][q] = 0.f; }
        #pragma unroll
        for (int kt = 0; kt < 8; kt++) {
            int cA = kt * 8 + (lane & 3);
            unsigned a[4];
            a[0] = __float_as_uint(hs[(r0 + rA) * 68 + cA]);
            a[1] = __float_as_uint(hs[(r0 + 8 + rA) * 68 + cA]);
            a[2] = __float_as_uint(hs[(r0 + rA) * 68 + cA + 4]);
            a[3] = __float_as_uint(hs[(r0 + 8 + rA) * 68 + cA + 4]);
            #pragma unroll
            for (int nt = 0; nt < 4; nt++) {
                float2 bq = ((const float2*)g_fMq)[(kt * 8 + nh * 4 + nt) * 32 + lane];
                float2 bk = ((const float2*)g_fMk)[(kt * 8 + nh * 4 + nt) * 32 + lane];
                MMA_TF32(aq[nt], a, __float_as_uint(bq.x), __float_as_uint(bq.y));
                MMA_TF32(ak[nt], a, __float_as_uint(bk.x), __float_as_uint(bk.y));
            }
        }
        #pragma unroll
        for (int nt = 0; nt < 4; nt++) {
            int col = n0 + nt * 8 + cb;
            float ba0 = att_b1[col], ba1 = att_b1[col + 1];
            xs[(r0 + rA) * 68 + col]       = __uint_as_float(f2tf32(fmaxf(aq[nt][0] - ak[nt][0] + ba0, 0.f)));
            xs[(r0 + rA) * 68 + col + 1]   = __uint_as_float(f2tf32(fmaxf(aq[nt][1] - ak[nt][1] + ba1, 0.f)));
            xs[(r0 + 8 + rA) * 68 + col]     = __uint_as_float(f2tf32(fmaxf(aq[nt][2] - ak[nt][2] + ba0, 0.f)));
            xs[(r0 + 8 + rA) * 68 + col + 1] = __uint_as_float(f2tf32(fmaxf(aq[nt][3] - ak[nt][3] + ba1, 0.f)));
            if (ok0) {
                *(float2*)(g_Q1 + (size_t)rowg0 * C + col) = make_float2(aq[nt][0], aq[nt][1]);
                *(float2*)(g_K1 + (size_t)rowg0 * C + col) = make_float2(ak[nt][0], ak[nt][1]);
            }
            if (ok1) {
                *(float2*)(g_Q1 + (size_t)rowg1 * C + col) = make_float2(aq[nt][2], aq[nt][3]);
                *(float2*)(g_K1 + (size_t)rowg1 * C + col) = make_float2(ak[nt][2], ak[nt][3]);
            }
        }
    }
    __syncthreads();

    {
        float acc[4][4];
        #pragma unroll
        for (int nt = 0; nt < 4; nt++) {
            int col = n0 + nt * 8 + cb;
            float b0 = att_b2[col], b1 = att_b2[col + 1];
            acc[nt][0] = b0; acc[nt][1] = b1; acc[nt][2] = b0; acc[nt][3] = b1;
        }
        #pragma unroll
        for (int kt = 0; kt < 8; kt++) {
            int cA = kt * 8 + (lane & 3);
            unsigned a[4];
            a[0] = __float_as_uint(xs[(r0 + rA) * 68 + cA]);
            a[1] = __float_as_uint(xs[(r0 + 8 + rA) * 68 + cA]);
            a[2] = __float_as_uint(xs[(r0 + rA) * 68 + cA + 4]);
            a[3] = __float_as_uint(xs[(r0 + 8 + rA) * 68 + cA + 4]);
            #pragma unroll
            for (int nt = 0; nt < 4; nt++) {
                float2 b = ((const float2*)g_fW2a)[(kt * 8 + nh * 4 + nt) * 32 + lane];
                MMA_TF32(acc[nt], a, __float_as_uint(b.x), __float_as_uint(b.y));
            }
        }
        #pragma unroll
        for (int nt = 0; nt < 4; nt++) {
            int col = n0 + nt * 8 + cb;
            float d0 = g_delta0[col], d1 = g_delta0[col + 1];
            float e0 = __expf(fmaxf(acc[nt][0], 0.f));
            float e1 = __expf(fmaxf(acc[nt][1], 0.f));
            float e2 = __expf(fmaxf(acc[nt][2], 0.f));
            float e3 = __expf(fmaxf(acc[nt][3], 0.f));
            if (ok0) {
                float v0 = vs[(r0 + rA) * 68 + col];
                float v1 = vs[(r0 + rA) * 68 + col + 1];
                *(float2*)(g_den + (size_t)rowg0 * C + col) = make_float2(e0, e1);
                *(float2*)(g_num + (size_t)rowg0 * C + col) = make_float2(e0 * (v0 + d0), e1 * (v1 + d1));
            }
            if (ok1) {
                float v2 = vs[(r0 + 8 + rA) * 68 + col];
                float v3 = vs[(r0 + 8 + rA) * 68 + col + 1];
                *(float2*)(g_den + (size_t)rowg1 * C + col) = make_float2(e2, e3);
                *(float2*)(g_num + (size_t)rowg1 * C + col) = make_float2(e2 * (v2 + d0), e3 * (v3 + d1));
            }
        }
    }
}

// ---------------- K2: edge kernel — dst-sorted, CONTIGUOUS-CHUNK schedule -------
__global__ void __launch_bounds__(256, 2)
edge_kernel(const float* __restrict__ att_b1, const float* __restrict__ pos_b1,
            const float* __restrict__ att_b2, const float* __restrict__ pos_b2,
            int E)
{
    extern __shared__ float smE[];
    float* hidA = smE;
    float* hidP = smE + 4352;
    float* exA  = smE + 8704;
    float* dlP  = smE + 13056;
    int2*  edB  = (int2*)(smE + 17408);   // [2][64]

    int tid  = threadIdx.x;
    int lane = tid & 31;
    int wid  = tid >> 5;
    bool isA = (wid < 4);
    int sub  = wid & 3;
    int n0b  = (sub & 1) * 32;
    int mp   = sub >> 1;
    int r0m  = mp * 16;
    int r1m  = (mp + 2) * 16;

    const float* w2 = isA ? g_w2a_t : g_w2p_t;
    const float* b2 = isA ? att_b2 : pos_b2;
    float* hid = isA ? hidA : hidP;
    float* res = isA ? exA  : dlP;

    unsigned bB[8][4][2];
    #pragma unroll
    for (int kt = 0; kt < 8; kt++) {
        #pragma unroll
        for (int nt = 0; nt < 4; nt++) {
            int k0 = kt * 8, n0 = n0b + nt * 8;
            bB[kt][nt][0] = f2tf32(w2[(k0 + (lane & 3)) * 64 + n0 + (lane >> 2)]);
            bB[kt][nt][1] = f2tf32(w2[(k0 + (lane & 3) + 4) * 64 + n0 + (lane >> 2)]);
        }
    }
    float bias0[4], bias1[4];
    #pragma unroll
    for (int nt = 0; nt < 4; nt++) {
        int col = n0b + nt * 8 + 2 * (lane & 3);
        bias0[nt] = b2[col];
        bias1[nt] = b2[col + 1];
    }

    // gather/scatter role: group of 16 lanes owns 4 CONSECUTIVE edges
    int grp = tid >> 4;
    int js  = (tid & 15) << 2;
    int eb  = grp << 2;
    float4 ba1 = *(const float4*)(att_b1 + js);
    float4 bp1 = *(const float4*)(pos_b1 + js);

    int sPrev[4], dPrev[4];
    #pragma unroll
    for (int k = 0; k < 4; k++) dPrev[k] = -1;

    int ntiles = (E + 63) >> 6;
    // contiguous chunk per block: disjoint dst ranges across concurrent blocks
    int t0 = (int)(((long long)blockIdx.x * ntiles) / gridDim.x);
    int t1 = (int)(((long long)(blockIdx.x + 1) * ntiles) / gridDim.x);

    {
        if (tid < 64 && t0 < t1) {
            int e = (t0 << 6) + tid;
            edB[tid] = (e < E) ? g_es[e] : make_int2(0, -1);
        }
    }
    __syncthreads();

    int it = 0;
    for (int tile = t0; tile < t1; tile++, it ^= 1) {
        // ===== PHASE A: merged scatter(prev) + gather(cur) + idx prefetch =====
        {
            float4 nAcc, dAcc;
            int curD = -1;
            #pragma unroll
            for (int k = 0; k < 4; k++) {
                int d = dPrev[k];
                if (d >= 0) {
                    int e = eb + k;
                    float4 ex = *(const float4*)(exA + e * 68 + js);
                    float4 dl = *(const float4*)(dlP + e * 68 + js);
                    float4 vv = *(const float4*)(g_v + (size_t)sPrev[k] * C + js);
                    float4 nv;
                    nv.x = ex.x * (vv.x + dl.x);
                    nv.y = ex.y * (vv.y + dl.y);
                    nv.z = ex.z * (vv.z + dl.z);
                    nv.w = ex.w * (vv.w + dl.w);
                    if (d == curD) {
                        nAcc.x += nv.x; nAcc.y += nv.y; nAcc.z += nv.z; nAcc.w += nv.w;
                        dAcc.x += ex.x; dAcc.y += ex.y; dAcc.z += ex.z; dAcc.w += ex.w;
                    } else {
                        if (curD >= 0) {
                            float* nr = g_num + (size_t)curD * C + js;
                            float* dr = g_den + (size_t)curD * C + js;
                            asm volatile("red.global.add.v4.f32 [%0], {%1,%2,%3,%4};"
                                         :: "l"(nr), "f"(nAcc.x), "f"(nAcc.y), "f"(nAcc.z), "f"(nAcc.w)
                                         : "memory");
                            asm volatile("red.global.add.v4.f32 [%0], {%1,%2,%3,%4};"
                                         :: "l"(dr), "f"(dAcc.x), "f"(dAcc.y), "f"(dAcc.z), "f"(dAcc.w)
                                         : "memory");
                        }
                        curD = d;
                        nAcc = nv;
                        dAcc = ex;
                    }
                }
            }
            if (curD >= 0) {
                float* nr = g_num + (size_t)curD * C + js;
                float* dr = g_den + (size_t)curD * C + js;
                asm volatile("red.global.add.v4.f32 [%0], {%1,%2,%3,%4};"
                             :: "l"(nr), "f"(nAcc.x), "f"(nAcc.y), "f"(nAcc.z), "f"(nAcc.w)
                             : "memory");
                asm volatile("red.global.add.v4.f32 [%0], {%1,%2,%3,%4};"
                             :: "l"(dr), "f"(dAcc.x), "f"(dAcc.y), "f"(dAcc.z), "f"(dAcc.w)
                             : "memory");
            }
        }
        // gather of current tile: dst-side loads dedup'd across consecutive edges
        {
            int dLast = -1;
            float4 qv, pd;
            #pragma unroll
            for (int k = 0; k < 4; k++) {
                int e = eb + k;
                int2 ed = edB[it * 64 + e];
                int s = ed.x, d = ed.y;
                sPrev[k] = s;
                dPrev[k] = d;
                int dc = d < 0 ? 0 : d;
                if (dc != dLast) {
                    qv = *(const float4*)(g_Q1 + (size_t)dc * C + js);
                    pd = *(const float4*)(g_P1 + (size_t)dc * C + js);
                    dLast = dc;
                }
                float4 kv = *(const float4*)(g_K1 + (size_t)s * C + js);
                float4 ps = *(const float4*)(g_P1 + (size_t)s * C + js);
                float4 ra, rp;
                ra.x = __uint_as_float(f2tf32(fmaxf(qv.x - kv.x + ba1.x, 0.f)));
                ra.y = __uint_as_float(f2tf32(fmaxf(qv.y - kv.y + ba1.y, 0.f)));
                ra.z = __uint_as_float(f2tf32(fmaxf(qv.z - kv.z + ba1.z, 0.f)));
                ra.w = __uint_as_float(f2tf32(fmaxf(qv.w - kv.w + ba1.w, 0.f)));
                rp.x = __uint_as_float(f2tf32(fmaxf(pd.x - ps.x + bp1.x, 0.f)));
                rp.y = __uint_as_float(f2tf32(fmaxf(pd.y - ps.y + bp1.y, 0.f)));
                rp.z = __uint_as_float(f2tf32(fmaxf(pd.z - ps.z + bp1.z, 0.f)));
                rp.w = __uint_as_float(f2tf32(fmaxf(pd.w - ps.w + bp1.w, 0.f)));
                if (d < 0) {
                    ra = make_float4(0.f, 0.f, 0.f, 0.f);
                    rp = ra;
                }
                *(float4*)(hidA + e * 68 + js) = ra;
                *(float4*)(hidP + e * 68 + js) = rp;
            }
        }
        {
            int ntile = tile + 1;
            if (ntile < t1 && tid < 64) {
                int e = (ntile << 6) + tid;
                edB[(it ^ 1) * 64 + tid] = (e < E) ? g_es[e] : make_int2(0, -1);
            }
        }
        __syncthreads();

        // ===== PHASE B: tensor-core MMA + epilogue -> exA/dlP =====
        float acc[2][4][4];
        #pragma unroll
        for (int s2 = 0; s2 < 2; s2++)
            #pragma unroll
            for (int nt = 0; nt < 4; nt++) {
                acc[s2][nt][0] = bias0[nt];
                acc[s2][nt][1] = bias1[nt];
                acc[s2][nt][2] = bias0[nt];
                acc[s2][nt][3] = bias1[nt];
            }
        int rA = lane >> 2;
        #pragma unroll
        for (int kt = 0; kt < 8; kt++) {
            int cA = kt * 8 + (lane & 3);
            unsigned a[2][4];
            a[0][0] = __float_as_uint(hid[(r0m + rA) * 68 + cA]);
            a[0][1] = __float_as_uint(hid[(r0m + 8 + rA) * 68 + cA]);
            a[0][2] = __float_as_uint(hid[(r0m + rA) * 68 + cA + 4]);
            a[0][3] = __float_as_uint(hid[(r0m + 8 + rA) * 68 + cA + 4]);
            a[1][0] = __float_as_uint(hid[(r1m + rA) * 68 + cA]);
            a[1][1] = __float_as_uint(hid[(r1m + 8 + rA) * 68 + cA]);
            a[1][2] = __float_as_uint(hid[(r1m + rA) * 68 + cA + 4]);
            a[1][3] = __float_as_uint(hid[(r1m + 8 + rA) * 68 + cA + 4]);
            #pragma unroll
            for (int s2 = 0; s2 < 2; s2++)
                #pragma unroll
                for (int nt = 0; nt < 4; nt++)
                    MMA_TF32(acc[s2][nt], a[s2], bB[kt][nt][0], bB[kt][nt][1]);
        }
        {
            int cbv = 2 * (lane & 3);
            #pragma unroll
            for (int s2 = 0; s2 < 2; s2++) {
                int rb = (s2 ? r1m : r0m) + rA;
                #pragma unroll
                for (int nt = 0; nt < 4; nt++) {
                    int col = n0b + nt * 8 + cbv;
                    float v0, v1, v2, v3;
                    if (isA) {
                        v0 = __expf(fmaxf(acc[s2][nt][0], 0.f));
                        v1 = __expf(fmaxf(acc[s2][nt][1], 0.f));
                        v2 = __expf(fmaxf(acc[s2][nt][2], 0.f));
                        v3 = __expf(fmaxf(acc[s2][nt][3], 0.f));
                    } else {
                        v0 = fmaxf(acc[s2][nt][0], 0.f);
                        v1 = fmaxf(acc[s2][nt][1], 0.f);
                        v2 = fmaxf(acc[s2][nt][2], 0.f);
                        v3 = fmaxf(acc[s2][nt][3], 0.f);
                    }
                    res[rb * 68 + col]           = v0;
                    res[rb * 68 + col + 1]       = v1;
                    res[(rb + 8) * 68 + col]     = v2;
                    res[(rb + 8) * 68 + col + 1] = v3;
                }
            }
        }
        __syncthreads();
    }

    // ===== pipeline drain: merged scatter of the final tile =====
    {
        float4 nAcc, dAcc;
        int curD = -1;
        #pragma unroll
        for (int k = 0; k < 4; k++) {
            int d = dPrev[k];
            if (d >= 0) {
                int e = eb + k;
                float4 ex = *(const float4*)(exA + e * 68 + js);
                float4 dl = *(const float4*)(dlP + e * 68 + js);
                float4 vv = *(const float4*)(g_v + (size_t)sPrev[k] * C + js);
                float4 nv;
                nv.x = ex.x * (vv.x + dl.x);
                nv.y = ex.y * (vv.y + dl.y);
                nv.z = ex.z * (vv.z + dl.z);
                nv.w = ex.w * (vv.w + dl.w);
                if (d == curD) {
                    nAcc.x += nv.x; nAcc.y += nv.y; nAcc.z += nv.z; nAcc.w += nv.w;
                    dAcc.x += ex.x; dAcc.y += ex.y; dAcc.z += ex.z; dAcc.w += ex.w;
                } else {
                    if (curD >= 0) {
                        float* nr = g_num + (size_t)curD * C + js;
                        float* dr = g_den + (size_t)curD * C + js;
                        asm volatile("red.global.add.v4.f32 [%0], {%1,%2,%3,%4};"
                                     :: "l"(nr), "f"(nAcc.x), "f"(nAcc.y), "f"(nAcc.z), "f"(nAcc.w)
                                     : "memory");
                        asm volatile("red.global.add.v4.f32 [%0], {%1,%2,%3,%4};"
                                     :: "l"(dr), "f"(dAcc.x), "f"(dAcc.y), "f"(dAcc.z), "f"(dAcc.w)
                                     : "memory");
                    }
                    curD = d;
                    nAcc = nv;
                    dAcc = ex;
                }
            }
        }
        if (curD >= 0) {
            float* nr = g_num + (size_t)curD * C + js;
            float* dr = g_den + (size_t)curD * C + js;
            asm volatile("red.global.add.v4.f32 [%0], {%1,%2,%3,%4};"
                         :: "l"(nr), "f"(nAcc.x), "f"(nAcc.y), "f"(nAcc.z), "f"(nAcc.w)
                         : "memory");
            asm volatile("red.global.add.v4.f32 [%0], {%1,%2,%3,%4};"
                         :: "l"(dr), "f"(dAcc.x), "f"(dAcc.y), "f"(dAcc.z), "f"(dAcc.w)
                         : "memory");
        }
    }
}

// ---------------- K3: out kernel — tf32 MMA over 64-node tiles ------------------
__global__ void __launch_bounds__(256)
out_kernel(const float* __restrict__ b_out, float* __restrict__ out, int n)
{
    __shared__ float rs[64 * 68];
    int tid  = threadIdx.x;
    int lane = tid & 31;
    int wid  = tid >> 5;
    int base = blockIdx.x * 64;

    for (int t = tid; t < 1024; t += 256) {
        int row = t >> 4;
        int col = (t & 15) * 4;
        int node = base + row;
        float4 r = make_float4(0.f, 0.f, 0.f, 0.f);
        if (node < n) {
            float4 nu = *(const float4*)(g_num + (size_t)node * C + col);
            float4 de = *(const float4*)(g_den + (size_t)node * C + col);
            r.x = __uint_as_float(f2tf32(nu.x / (de.x + 1e-16f)));
            r.y = __uint_as_float(f2tf32(nu.y / (de.y + 1e-16f)));
            r.z = __uint_as_float(f2tf32(nu.z / (de.z + 1e-16f)));
            r.w = __uint_as_float(f2tf32(nu.w / (de.w + 1e-16f)));
        }
        *(float4*)(rs + row * 68 + col) = r;
    }
    __syncthreads();

    int r0 = (wid & 3) * 16;
    int nh = wid >> 2;
    int n0 = nh * 32;
    int rA = lane >> 2;
    int cb = 2 * (lane & 3);
    int rowg0 = base + r0 + rA;
    int rowg1 = rowg0 + 8;

    float acc[4][4];
    #pragma unroll
    for (int nt = 0; nt < 4; nt++) {
        int col = n0 + nt * 8 + cb;
        float b0 = b_out[col], b1 = b_out[col + 1];
        acc[nt][0] = b0; acc[nt][1] = b1; acc[nt][2] = b0; acc[nt][3] = b1;
    }
    #pragma unroll
    for (int kt = 0; kt < 8; kt++) {
        int cA = kt * 8 + (lane & 3);
        unsigned a[4];
        a[0] = __float_as_uint(rs[(r0 + rA) * 68 + cA]);
        a[1] = __float_as_uint(rs[(r0 + 8 + rA) * 68 + cA]);
        a[2] = __float_as_uint(rs[(r0 + rA) * 68 + cA + 4]);
        a[3] = __float_as_uint(rs[(r0 + 8 + rA) * 68 + cA + 4]);
        #pragma unroll
        for (int nt = 0; nt < 4; nt++) {
            float2 b = ((const float2*)g_fWout)[(kt * 8 + nh * 4 + nt) * 32 + lane];
            MMA_TF32(acc[nt], a, __float_as_uint(b.x), __float_as_uint(b.y));
        }
    }
    #pragma unroll
    for (int nt = 0; nt < 4; nt++) {
        int col = n0 + nt * 8 + cb;
        if (rowg0 < n)
            *(float2*)(out + (size_t)rowg0 * C + col) =
                make_float2(fmaxf(acc[nt][0], 0.f), fmaxf(acc[nt][1], 0.f));
        if (rowg1 < n)
            *(float2*)(out + (size_t)rowg1 * C + col) =
                make_float2(fmaxf(acc[nt][2], 0.f), fmaxf(acc[nt][3], 0.f));
    }
}

// ---------------- launch --------------------------------------------------------
extern "C" void kernel_launch(void* const* d_in, const int* in_sizes, int n_in,
                              void* d_out, int out_size)
{
    const float* x      = (const float*)d_in[0];
    const float* pos    = (const float*)d_in[1];
    const int*   ei     = (const int*)  d_in[2];
    const float* W_in   = (const float*)d_in[3];
    const float* b_in   = (const float*)d_in[4];
    const float* W_out  = (const float*)d_in[5];
    const float* b_out  = (const float*)d_in[6];
    const float* W_lin  = (const float*)d_in[7];
    const float* W_src  = (const float*)d_in[8];
    const float* W_dst  = (const float*)d_in[9];
    const float* pos_w1 = (const float*)d_in[10];
    const float* pos_b1 = (const float*)d_in[11];
    const float* pos_w2 = (const float*)d_in[12];
    const float* pos_b2 = (const float*)d_in[13];
    const float* att_w1 = (const float*)d_in[14];
    const float* att_b1 = (const float*)d_in[15];
    const float* att_w2 = (const float*)d_in[16];
    const float* att_b2 = (const float*)d_in[17];

    int n = in_sizes[0] / C;
    int E = in_sizes[2] / 2;
    const int* srcArr = ei;
    const int* dstArr = ei + E;

    size_t smemNode = (size_t)(3 * 64 * 68) * sizeof(float);          // 52224
    size_t smemEdge = (size_t)(4 * 64 * 68) * sizeof(float) + 1024;   // 70656
    cudaFuncSetAttribute(node_kernel, cudaFuncAttributeMaxDynamicSharedMemorySize, (int)smemNode);
    cudaFuncSetAttribute(edge_kernel, cudaFuncAttributeMaxDynamicSharedMemorySize, (int)smemEdge);

    int tilesN = (n + 63) / 64;

    // edge sort by dst (counting sort)
    zero_cnt_kernel<<<(n + 255) / 256, 256>>>(n);
    hist_kernel<<<(E + 255) / 256, 256>>>(dstArr, E);
    scan_kernel<<<1, 1024>>>(n);
    reorder_kernel<<<(E + 255) / 256, 256>>>(srcArr, dstArr, E);

    prep_kernel<<<1, 256>>>(att_w1, W_dst, W_src, W_in, W_lin, att_w2, pos_w2, W_out,
                            pos_b1, pos_b2);
    node_kernel<<<tilesN, 256, smemNode>>>(x, pos, pos_w1, b_in, att_b1, att_b2, n);
    edge_kernel<<<296, 256, smemEdge>>>(att_b1, pos_b1, att_b2, pos_b2, E);
    out_kernel<<<tilesN, 256>>>(b_out, (float*)d_out, n);
}